// round 2
// baseline (speedup 1.0000x reference)
#include <cuda_runtime.h>
#include <math.h>

// Hausdorff, D=H=W=20, V=8000, batch 2.
// Integer squared-distance separable EDT (exact); sqrt/20 only on 4 final maxima.
// Single kernel launch: 4 blocks (one per transform t = n*2+m), last block finalizes.

#define VV 8000
#define INF_S 32000   // "infinity" for squared distances (max legit = 3*19^2 = 1083)

__device__ int g_max2[2][2] = {{-1,-1},{-1,-1}}; // [n][0]=max over A-only of d2(.,B); [n][1]=B-only->A
__device__ int g_anyA[2]    = {0, 0};
__device__ int g_count      = 0;

__global__ void __launch_bounds__(1024, 1)
haus_all(const float* __restrict__ predict,
         const float* __restrict__ targetp,
         float* __restrict__ out)
{
    __shared__ unsigned char mS[VV];   // mask of the set we transform (A if m==0, B if m==1)
    __shared__ unsigned char mO[VV];   // the other mask
    __shared__ short F1[VV];
    __shared__ short F2[VV];
    __shared__ int   sred;
    __shared__ int   sany;

    const int t = blockIdx.x;          // 0..3
    const int n = t >> 1, m = t & 1;
    const float* setSrc = (m ? targetp : predict) + n * VV;
    const float* othSrc = (m ? predict : targetp) + n * VV;
    const int tid = threadIdx.x;

    if (tid == 0) { sred = -1; sany = 0; }

    // masks (jnp.round == round-half-even == rintf)
    for (int v = tid; v < VV; v += 1024) {
        mS[v] = (rintf(setSrc[v]) != 0.0f) ? 1 : 0;
        mO[v] = (rintf(othSrc[v]) != 0.0f) ? 1 : 0;
    }
    __syncthreads();

    // z-pass: F1(x,y,z) = min_zp mS(x,y,zp) ? (z-zp)^2 : INF
    for (int v = tid; v < VV; v += 1024) {
        int z = v % 20;
        int rowBase = v - z;
        int best = INF_S;
        #pragma unroll
        for (int zp = 0; zp < 20; zp++) {
            int dz = z - zp;
            int cand = mS[rowBase + zp] ? dz * dz : INF_S;
            best = min(best, cand);
        }
        F1[v] = (short)best;
    }
    __syncthreads();

    // y-pass: F2(x,y,z) = min_yp F1(x,yp,z) + (y-yp)^2   (capped at INF_S)
    for (int v = tid; v < VV; v += 1024) {
        int z = v % 20;
        int y = (v / 20) % 20;
        int base = v - y * 20;             // x*400 + z
        int best = INF_S;
        #pragma unroll
        for (int yp = 0; yp < 20; yp++) {
            int dy = y - yp;
            best = min(best, (int)F1[base + yp * 20] + dy * dy);
        }
        F2[v] = (short)min(best, INF_S);
    }
    __syncthreads();

    // x-pass + classify + reduce
    int localMax = -1;
    int localAny = 0;
    for (int v = tid; v < VV; v += 1024) {
        int x  = v / 400;
        int yz = v % 400;
        int best = INF_S + 400;
        #pragma unroll
        for (int xp = 0; xp < 20; xp++) {
            int dx = x - xp;
            best = min(best, (int)F2[xp * 400 + yz] + dx * dx);
        }
        int s = mS[v], o = mO[v];
        if (o && !s) localMax = max(localMax, best);  // "other-only" points
        if (m == 0) localAny |= s;                    // s == mask A here
    }
    localMax = __reduce_max_sync(0xffffffffu, localMax);
    localAny = __any_sync(0xffffffffu, localAny);
    if ((tid & 31) == 0) {
        if (localMax >= 0) atomicMax(&sred, localMax);
        if (localAny)      atomicOr(&sany, 1);
    }
    __syncthreads();

    if (tid == 0) {
        if (sred >= 0) atomicMax(&g_max2[n][1 - m], sred);
        if (m == 0 && sany) atomicOr(&g_anyA[n], 1);
        __threadfence();
        int done = atomicAdd(&g_count, 1);
        if (done == 3) {
            // last block: finalize (atomic reads to bypass any L1 staleness)
            float sum = 0.0f;
            #pragma unroll
            for (int nn = 0; nn < 2; nn++) {
                int a2   = atomicAdd(&g_max2[nn][0], 0);
                int b2   = atomicAdd(&g_max2[nn][1], 0);
                int anyA = atomicAdd(&g_anyA[nn], 0);
                float dA = 0.0f;
                if (a2 >= 0) dA = (a2 > 1083) ? 1e9f : sqrtf((float)a2) * 0.05f;
                float dB = 0.0f;
                if (b2 >= 0) dB = anyA ? ((b2 > 1083) ? 1e9f : sqrtf((float)b2) * 0.05f)
                                       : 999.0f;
                sum += fmaxf(dA, dB);
                g_max2[nn][0] = -1; g_max2[nn][1] = -1; g_anyA[nn] = 0;
            }
            out[0] = sum * 0.5f;
            g_count = 0;   // restore static-init state for next replay
        }
    }
}

extern "C" void kernel_launch(void* const* d_in, const int* in_sizes, int n_in,
                              void* d_out, int out_size)
{
    const float* predict = (const float*)d_in[0];
    const float* targetp = (const float*)d_in[1];
    haus_all<<<4, 1024>>>(predict, targetp, (float*)d_out);
}

// round 3
// speedup vs baseline: 1.8576x; 1.8576x over previous
#include <cuda_runtime.h>
#include <math.h>

// Hausdorff, D=H=W=20, V=8000, batch 2.
// Exact integer squared-distance separable EDT; sqrt/20 only on final maxima.
// ONE launch, 80 blocks (4 transforms x 20 x-slabs), software grid barrier
// between the {z,y}-pass phase and the {x-pass, reduce, finalize} phase.
// All 80 blocks are co-resident (grid < 148 SMs) -> spin barrier is safe.

#define VV 8000
#define INF_S 32000   // squared-distance "infinity" (max legit = 3*19^2 = 1083)

__device__ int g_F2[4][VV];                               // after z+y passes
__device__ int g_max2[2][2] = {{-1,-1},{-1,-1}};          // [n][0]=A-only->B, [n][1]=B-only->A
__device__ int g_anyA[2]    = {0, 0};
__device__ int g_bar        = 0;                          // grid barrier counter
__device__ int g_done       = 0;                          // completion counter

__global__ void __launch_bounds__(416, 1)
haus_one(const float* __restrict__ predict,
         const float* __restrict__ targetp,
         float* __restrict__ out)
{
    __shared__ unsigned char mS[400];   // set mask for this slab (A if m==0 else B)
    __shared__ unsigned char mO[400];   // other mask for this slab
    __shared__ short F1[400];
    __shared__ int   sred, sany;

    const int b = blockIdx.x;           // t*20 + x
    const int t = b / 20, x = b % 20;
    const int n = t >> 1, m = t & 1;
    const float* setSrc = (m ? targetp : predict) + n * VV + x * 400;
    const float* othSrc = (m ? predict : targetp) + n * VV + x * 400;
    const int tid = threadIdx.x;

    if (tid == 0) { sred = -1; sany = 0; }

    // ---- Phase 1: masks + z-pass + y-pass (SMEM), emit F2 to global ----
    if (tid < 400) {
        // jnp.round == round-half-even == rintf
        mS[tid] = (rintf(setSrc[tid]) != 0.0f) ? 1 : 0;
        mO[tid] = (rintf(othSrc[tid]) != 0.0f) ? 1 : 0;
    }
    __syncthreads();

    if (tid < 400) {
        int z = tid % 20, base = tid - z;
        int best = INF_S;
        #pragma unroll
        for (int zp = 0; zp < 20; zp++) {
            int dz = z - zp;
            int cand = mS[base + zp] ? dz * dz : INF_S;
            best = min(best, cand);
        }
        F1[tid] = (short)best;
    }
    __syncthreads();

    if (tid < 400) {
        int z = tid % 20, y = tid / 20;
        int best = INF_S;
        #pragma unroll
        for (int yp = 0; yp < 20; yp++) {
            int dy = y - yp;
            best = min(best, (int)F1[yp * 20 + z] + dy * dy);
        }
        g_F2[t][x * 400 + tid] = min(best, INF_S);
    }
    __syncthreads();

    // ---- Grid barrier (all 80 blocks co-resident) ----
    if (tid == 0) {
        __threadfence();
        atomicAdd(&g_bar, 1);
        while (atomicAdd(&g_bar, 0) < 80) { }
        __threadfence();
    }
    __syncthreads();

    // ---- Phase 2: x-pass + classification + reduction ----
    int localMax = -1, localAny = 0;
    if (tid < 400) {
        const int* __restrict__ f2 = g_F2[t];
        int best = 1 << 29;
        #pragma unroll
        for (int xp = 0; xp < 20; xp++) {
            int dx = x - xp;
            best = min(best, f2[xp * 400 + tid] + dx * dx);
        }
        int s = mS[tid], o = mO[tid];
        if (o && !s) localMax = best;   // "other-only" point of this transform
        if (m == 0)  localAny = s;      // s == mask A when m==0
    }
    localMax = __reduce_max_sync(0xffffffffu, localMax);
    localAny = __any_sync(0xffffffffu, localAny);
    if ((tid & 31) == 0) {
        if (localMax >= 0) atomicMax(&sred, localMax);
        if (localAny)      atomicOr(&sany, 1);
    }
    __syncthreads();

    if (tid == 0) {
        if (sred >= 0)       atomicMax(&g_max2[n][1 - m], sred);
        if (m == 0 && sany)  atomicOr(&g_anyA[n], 1);
        __threadfence();
        int done = atomicAdd(&g_done, 1);
        if (done == 79) {
            // last block finalizes (atomic reads for coherence)
            float sum = 0.0f;
            #pragma unroll
            for (int nn = 0; nn < 2; nn++) {
                int a2   = atomicAdd(&g_max2[nn][0], 0);
                int b2   = atomicAdd(&g_max2[nn][1], 0);
                int anyA = atomicAdd(&g_anyA[nn], 0);
                float dA = 0.0f;
                if (a2 >= 0) dA = (a2 > 1083) ? 1e9f : sqrtf((float)a2) * 0.05f;
                float dB = 0.0f;
                if (b2 >= 0) dB = anyA ? ((b2 > 1083) ? 1e9f : sqrtf((float)b2) * 0.05f)
                                       : 999.0f;
                sum += fmaxf(dA, dB);
                g_max2[nn][0] = -1; g_max2[nn][1] = -1; g_anyA[nn] = 0;
            }
            out[0] = sum * 0.5f;
            g_bar = 0;    // every block has passed the barrier (done==79 proves it)
            g_done = 0;   // restore static-init state for the next graph replay
        }
    }
}

extern "C" void kernel_launch(void* const* d_in, const int* in_sizes, int n_in,
                              void* d_out, int out_size)
{
    const float* predict = (const float*)d_in[0];
    const float* targetp = (const float*)d_in[1];
    haus_one<<<80, 416>>>(predict, targetp, (float*)d_out);
}